// round 7
// baseline (speedup 1.0000x reference)
#include <cuda_runtime.h>
#include <cuda_bf16.h>

#define THREADS 256
#define WIN     9
#define EDGE    4
#define QPW     4          // queries per warp (8 lanes each)
#define B_MAX   131072
#define T_BINS  2048

__device__ int g_idx[B_MAX];
__device__ int g_perm[B_MAX];
__device__ int g_hist[T_BINS];
__device__ int g_cursor[T_BINS];

// ---------- nearest-anchor index: analytic + exact fp32 argmin verify ----------
__device__ __forceinline__ int nearest_idx(float xv, const float* __restrict__ etab, int T)
{
    const float e0 = __ldg(&etab[0]);
    const float eN = __ldg(&etab[T - 1]);
    const float step = (eN - e0) / (float)(T - 1);
    int i0 = (int)floorf((xv - e0) / step);
    int idx = 0;
    float best = 3.4e38f;
    #pragma unroll
    for (int k = 0; k < 4; k++) {
        int cc = min(max(i0 - 1 + k, 0), T - 1);
        float d = xv - __ldg(&etab[cc]);
        d *= d;
        if (d < best) { best = d; idx = cc; }   // strict '<' == argmin first-occurrence
    }
    return idx;
}

// ---------- pass Z: zero histogram ----------
__global__ void k_zero()
{
    int i = blockIdx.x * blockDim.x + threadIdx.x;
    if (i < T_BINS) g_hist[i] = 0;
}

// ---------- pass A: idx per query + histogram ----------
__global__ __launch_bounds__(256)
void k_index(const float* __restrict__ x, const float* __restrict__ etab, int B, int T)
{
    int q = blockIdx.x * blockDim.x + threadIdx.x;
    if (q >= B) return;
    int idx = nearest_idx(x[q], etab, T);
    g_idx[q] = idx;
    atomicAdd(&g_hist[idx], 1);
}

// ---------- pass B: exclusive prefix sum over 2048 bins (one block, 1024 thr) ----------
__global__ __launch_bounds__(1024)
void k_scan()
{
    __shared__ int s[1024];
    int i = threadIdx.x;
    int a = g_hist[2 * i];
    int b = g_hist[2 * i + 1];
    s[i] = a + b;
    #pragma unroll
    for (int off = 1; off < 1024; off <<= 1) {
        __syncthreads();
        int v = (i >= off) ? s[i - off] : 0;
        __syncthreads();
        s[i] += v;
    }
    __syncthreads();
    int excl_pair = s[i] - (a + b);      // exclusive sum of pairs before this pair
    g_cursor[2 * i]     = excl_pair;
    g_cursor[2 * i + 1] = excl_pair + a;
}

// ---------- pass C: scatter query ids into bin-sorted order ----------
__global__ __launch_bounds__(256)
void k_scatter(int B)
{
    int q = blockIdx.x * blockDim.x + threadIdx.x;
    if (q >= B) return;
    int pos = atomicAdd(&g_cursor[g_idx[q]], 1);
    g_perm[pos] = q;
}

// ---------- pass D: main kernel over anchor-sorted queries ----------
__global__ __launch_bounds__(THREADS, 8)
void hwnet_kernel(const float* __restrict__ x,
                  const float* __restrict__ etab,
                  const float* __restrict__ tctab,
                  const float* __restrict__ vtab,
                  float* __restrict__ out,
                  int B, int T)
{
    const int tid  = threadIdx.x;
    const int warp = tid >> 5;
    const int lane = tid & 31;
    const int pwarp = (blockIdx.x * (THREADS / 32) + warp) * QPW; // first sorted position

    // ---- Phase 1 (lanes 0..3): weights for this warp's 4 queries
    float wv[WIN];
    int base = 0;
    int gq   = 0;
    if (lane < QPW) {
        const int p = min(pwarp + lane, B - 1);
        gq = g_perm[p];
        const float xv = x[gq];
        const int idx = g_idx[gq];

        const float tc = __ldg(&tctab[idx]);            // UNCLIPPED idx (matches reference)
        const int idx_c = min(max(idx, EDGE), T - 1 - EDGE);
        base = idx_c - EDGE;

        float m = -3.4e38f;
        #pragma unroll
        for (int j = 0; j < WIN; j++) {
            float e = __ldg(&etab[base + j]);
            float d = xv - e;
            float l = -(d * d) * tc;
            wv[j] = l;
            m = fmaxf(m, l);
        }
        float sum = 0.0f;
        #pragma unroll
        for (int j = 0; j < WIN; j++) {
            float p2 = __expf(wv[j] - m);
            wv[j] = p2;
            sum += p2;
        }
        const float inv = __frcp_rn(sum);
        #pragma unroll
        for (int j = 0; j < WIN; j++) wv[j] *= inv;
    }

    // ---- Broadcast to the 8 lanes owning each query
    const int q   = lane >> 3;      // 0..3
    const int sub = lane & 7;       // 0..7: which 16B chunk of D=64
    base = __shfl_sync(0xffffffffu, base, q);
    gq   = __shfl_sync(0xffffffffu, gq,   q);
    #pragma unroll
    for (int j = 0; j < WIN; j++) wv[j] = __shfl_sync(0xffffffffu, wv[j], q);

    if (pwarp + q >= B) return;

    // ---- Phase 2: gather — sorted order makes the 4 query-groups hit the same lines
    const float4* vt = (const float4*)vtab;     // rows of 16 float4
    float4 a0 = make_float4(0.f, 0.f, 0.f, 0.f);
    float4 a1 = make_float4(0.f, 0.f, 0.f, 0.f);

    #pragma unroll
    for (int j = 0; j < WIN; j++) {
        const float4* row = vt + (size_t)(base + j) * 16;
        float4 v0 = __ldg(row + sub);
        float4 v1 = __ldg(row + 8 + sub);
        float wj = wv[j];
        a0.x = fmaf(wj, v0.x, a0.x);
        a0.y = fmaf(wj, v0.y, a0.y);
        a0.z = fmaf(wj, v0.z, a0.z);
        a0.w = fmaf(wj, v0.w, a0.w);
        a1.x = fmaf(wj, v1.x, a1.x);
        a1.y = fmaf(wj, v1.y, a1.y);
        a1.z = fmaf(wj, v1.z, a1.z);
        a1.w = fmaf(wj, v1.w, a1.w);
    }

    float4* o = (float4*)(out + (size_t)gq * 64);
    __stcs(o + sub,     a0);
    __stcs(o + 8 + sub, a1);
}

extern "C" void kernel_launch(void* const* d_in, const int* in_sizes, int n_in,
                              void* d_out, int out_size)
{
    const float* x     = (const float*)d_in[0];   // [B,1]
    const float* etab  = (const float*)d_in[1];   // [T,1]
    const float* tctab = (const float*)d_in[2];   // [T,1]
    const float* vtab  = (const float*)d_in[3];   // [T,D]
    float* out = (float*)d_out;

    const int B = in_sizes[0];                    // 131072
    const int T = in_sizes[1];                    // 2048

    k_zero<<<(T_BINS + 255) / 256, 256>>>();
    k_index<<<(B + 255) / 256, 256>>>(x, etab, B, T);
    k_scan<<<1, 1024>>>();
    k_scatter<<<(B + 255) / 256, 256>>>(B);

    const int qpb    = (THREADS / 32) * QPW;      // 32 queries per block
    const int blocks = (B + qpb - 1) / qpb;
    hwnet_kernel<<<blocks, THREADS>>>(x, etab, tctab, vtab, out, B, T);
}